// round 8
// baseline (speedup 1.0000x reference)
#include <cuda_runtime.h>
#include <stdint.h>

#define K 8
#define C 256
#define INF_F __int_as_float(0x7F800000)

// ---------------------------------------------------------------------------
// Scratch. Coarse point regions: stage2 [0,8192), stage1 [8192,10240),
// stage0 [10240,10752). Group regions: stage2 [0,256), stage1 [256,320),
// stage0 [320,336). Query code regions: lvl0 [0,32768), lvl1 [32768,40960),
// lvl2 [40960,43008).
// ---------------------------------------------------------------------------
static __device__ float4 g_cx[10752];
static __device__ float4 g_cn[10752];
static __device__ unsigned long long g_code[10752];    // coarse morton | idx
static __device__ unsigned long long g_qcode[43008];   // query morton | idx
static __device__ unsigned long long g_qsort[43008];   // bin-sorted queries
static __device__ float4 g_sx[10752];
static __device__ float4 g_sn[10752];
static __device__ int    g_sid[10752];
static __device__ float4 g_gc[336];                    // group center + radius
static __device__ float  g_wiv[2 * 16384 * 16 + 2 * 4096 * 16 + 2 * 1024 * 16];
static __device__ float  g_x1[2 * 1024 * 256];
static __device__ float  g_x2[2 * 4096 * 256];

#define WOFF2 0
#define WOFF1 (2 * 16384 * 16)
#define WOFF0 (2 * 16384 * 16 + 2 * 4096 * 16)

// ---------------------------------------------------------------------------
__device__ __forceinline__ unsigned expand_bits(unsigned v) {
    v &= 0x3FFu;
    v = (v | (v << 16)) & 0x030000FFu;
    v = (v | (v << 8))  & 0x0300F00Fu;
    v = (v | (v << 4))  & 0x030C30C3u;
    v = (v | (v << 2))  & 0x09249249u;
    return v;
}
__device__ __forceinline__ unsigned quant10(float x) {
    float u = (x + 4.2f) * (1024.0f / 8.4f);
    u = fminf(fmaxf(u, 0.0f), 1023.0f);
    return (unsigned)u;
}
__device__ __forceinline__ unsigned morton(float x, float y, float z) {
    return (expand_bits(quant10(x)) << 2) | (expand_bits(quant10(y)) << 1) |
           expand_bits(quant10(z));
}

// ---------------------------------------------------------------------------
// Fused pack: coarse levels (pack + code) and query codes, one launch.
// ---------------------------------------------------------------------------
__global__ void pack_kernel(const float* __restrict__ x0p, const float* __restrict__ x1p,
                            const float* __restrict__ n1p, const float* __restrict__ x2p,
                            const float* __restrict__ n2p, const float* __restrict__ x3p,
                            const float* __restrict__ n3p)
{
    int i = blockIdx.x * 256 + threadIdx.x;
    if (i < 10752) {
        const float* xs;
        const float* ns;
        int j, mask;
        if (i < 8192)       { xs = x1p; ns = n1p; j = i;         mask = 4095; }
        else if (i < 10240) { xs = x2p; ns = n2p; j = i - 8192;  mask = 1023; }
        else                { xs = x3p; ns = n3p; j = i - 10240; mask = 255;  }
        float x = xs[3 * j], y = xs[3 * j + 1], z = xs[3 * j + 2];
        g_cx[i] = make_float4(x, y, z, 0.5f * (x * x + y * y + z * z));
        float a = ns[3 * j], b = ns[3 * j + 1], c = ns[3 * j + 2];
        g_cn[i] = make_float4(a, b, c, 0.5f * (a * a + b * b + c * c));
        g_code[i] = ((unsigned long long)morton(x, y, z) << 32) |
                    (unsigned)(j & mask);
    } else if (i < 10752 + 43008) {
        int j = i - 10752;   // index into g_qcode
        const float* xs;
        int n;
        if (j < 32768)      { xs = x0p; n = j & 16383; }
        else if (j < 40960) { xs = x1p; n = (j - 32768) & 4095; }
        else                { xs = x2p; n = (j - 40960) & 1023; }
        int gj = (j < 32768) ? j : (j < 40960 ? (j - 32768) + ((j - 32768) >> 12) * 0 : 0);
        // recompute global element index directly:
        int gidx;
        if (j < 32768)      gidx = j;                 // b*16384 + n
        else if (j < 40960) gidx = j - 32768;         // b*4096 + n
        else                gidx = j - 40960;         // b*1024 + n
        (void)gj;
        float x = xs[3 * gidx], y = xs[3 * gidx + 1], z = xs[3 * gidx + 2];
        g_qcode[j] = ((unsigned long long)morton(x, y, z) << 32) | (unsigned)n;
    }
}

// ---------------------------------------------------------------------------
// Sort kernel: blocks 0-5 = coarse counting sort + reorder + spheres;
// blocks 6-11 = query counting sort (bin-level, locality only).
// ---------------------------------------------------------------------------
__global__ void __launch_bounds__(1024) csort_kernel()
{
    __shared__ unsigned long long skeys[4096];
    __shared__ int hist[4096];

    const int tid = threadIdx.x;

    if (blockIdx.x < 6) {
        static const int tb[6]   = {0, 4096, 8192, 9216, 10240, 10496};
        static const int ts[6]   = {4096, 4096, 1024, 1024, 256, 256};
        static const int tbin[6] = {2048, 2048, 512, 512, 128, 128};
        static const int tsh[6]  = {19, 19, 21, 21, 23, 23};
        static const int tgb[6]  = {0, 128, 256, 288, 320, 328};

        const int seg = blockIdx.x;
        const int base = tb[seg], S = ts[seg], bins = tbin[seg], shift = tsh[seg];

        for (int i = tid; i < S; i += 1024) skeys[i] = g_code[base + i];
        for (int i = tid; i < bins; i += 1024) hist[i] = 0;
        __syncthreads();
        for (int i = tid; i < S; i += 1024)
            atomicAdd(&hist[(unsigned)(skeys[i] >> 32) >> shift], 1);
        __syncthreads();
        for (int dstep = 1; dstep < bins; dstep <<= 1) {
            for (int i = tid; i < bins / (2 * dstep); i += 1024) {
                int idx = (i + 1) * 2 * dstep - 1;
                hist[idx] += hist[idx - dstep];
            }
            __syncthreads();
        }
        if (tid == 0) hist[bins - 1] = 0;
        __syncthreads();
        for (int dstep = bins >> 1; dstep >= 1; dstep >>= 1) {
            for (int i = tid; i < bins / (2 * dstep); i += 1024) {
                int idx = (i + 1) * 2 * dstep - 1;
                int t = hist[idx - dstep];
                hist[idx - dstep] = hist[idx];
                hist[idx] += t;
            }
            __syncthreads();
        }
        for (int i = tid; i < S; i += 1024) {
            unsigned long long key = skeys[i];
            int bin = (unsigned)(key >> 32) >> shift;
            int pos = atomicAdd(&hist[bin], 1);
            g_code[base + pos] = key;
        }
        __syncthreads();

        // reorder + bounding spheres
        int warp = tid >> 5, lane = tid & 31;
        int nG = S / 32;
        for (int g = warp; g < nG; g += 32) {
            unsigned long long key = g_code[base + g * 32 + lane];
            int li = (int)(unsigned)key;
            float4 v = g_cx[base + li];
            int dst = base + g * 32 + lane;
            g_sx[dst] = v;
            g_sn[dst] = g_cn[base + li];
            g_sid[dst] = li;

            float mnx = v.x, mxx = v.x, mny = v.y, mxy = v.y, mnz = v.z, mxz = v.z;
#pragma unroll
            for (int off = 16; off; off >>= 1) {
                mnx = fminf(mnx, __shfl_xor_sync(0xFFFFFFFFu, mnx, off));
                mxx = fmaxf(mxx, __shfl_xor_sync(0xFFFFFFFFu, mxx, off));
                mny = fminf(mny, __shfl_xor_sync(0xFFFFFFFFu, mny, off));
                mxy = fmaxf(mxy, __shfl_xor_sync(0xFFFFFFFFu, mxy, off));
                mnz = fminf(mnz, __shfl_xor_sync(0xFFFFFFFFu, mnz, off));
                mxz = fmaxf(mxz, __shfl_xor_sync(0xFFFFFFFFu, mxz, off));
            }
            float cxc = (mnx + mxx) * 0.5f, cyc = (mny + mxy) * 0.5f;
            float czc = (mnz + mxz) * 0.5f;
            float dx = v.x - cxc, dy = v.y - cyc, dz = v.z - czc;
            float d2 = fmaf(dx, dx, fmaf(dy, dy, dz * dz));
#pragma unroll
            for (int off = 16; off; off >>= 1)
                d2 = fmaxf(d2, __shfl_xor_sync(0xFFFFFFFFu, d2, off));
            if (lane == 0) g_gc[tgb[seg] + g] = make_float4(cxc, cyc, czc, sqrtf(d2));
        }
    } else {
        // ---- query bin sort (keys live in global; read twice) ----
        static const int qb[6]   = {0, 16384, 32768, 36864, 40960, 41984};
        static const int qs[6]   = {16384, 16384, 4096, 4096, 1024, 1024};
        static const int qbin[6] = {4096, 4096, 2048, 2048, 512, 512};
        static const int qsh[6]  = {18, 18, 19, 19, 21, 21};

        const int seg = blockIdx.x - 6;
        const int base = qb[seg], S = qs[seg], bins = qbin[seg], shift = qsh[seg];

        for (int i = tid; i < bins; i += 1024) hist[i] = 0;
        __syncthreads();
        for (int i = tid; i < S; i += 1024)
            atomicAdd(&hist[(unsigned)(g_qcode[base + i] >> 32) >> shift], 1);
        __syncthreads();
        for (int dstep = 1; dstep < bins; dstep <<= 1) {
            for (int i = tid; i < bins / (2 * dstep); i += 1024) {
                int idx = (i + 1) * 2 * dstep - 1;
                hist[idx] += hist[idx - dstep];
            }
            __syncthreads();
        }
        if (tid == 0) hist[bins - 1] = 0;
        __syncthreads();
        for (int dstep = bins >> 1; dstep >= 1; dstep >>= 1) {
            for (int i = tid; i < bins / (2 * dstep); i += 1024) {
                int idx = (i + 1) * 2 * dstep - 1;
                int t = hist[idx - dstep];
                hist[idx - dstep] = hist[idx];
                hist[idx] += t;
            }
            __syncthreads();
        }
        for (int i = tid; i < S; i += 1024) {
            unsigned long long key = g_qcode[base + i];
            int bin = (unsigned)(key >> 32) >> shift;
            int pos = atomicAdd(&hist[bin], 1);
            g_qsort[base + pos] = key;
        }
    }
}

// ---------------------------------------------------------------------------
// topk per-query: warp per query, sphere-pruned sweep with group prefetch.
// ---------------------------------------------------------------------------
template <int S, int G>
__device__ __forceinline__ void topk_query(
    const float* __restrict__ xyzF, const float* __restrict__ nrmF,
    int N, int base, int gbase, int wbase, int b, int n, int lane)
{
    const float4* __restrict__ sx = g_sx + base + b * S;
    const float4* __restrict__ sn = g_sn + base + b * S;
    const float4* __restrict__ gc = g_gc + gbase + b * G;

    const float* p = xyzF + ((size_t)b * N + n) * 3;
    const float qx = p[0], qy = p[1], qz = p[2];
    const float qh = 0.5f * (qx * qx + qy * qy + qz * qz);
    const float* q = nrmF + ((size_t)b * N + n) * 3;
    const float ux = q[0], uy = q[1], uz = q[2];
    const float uh = 0.5f * (ux * ux + uy * uy + uz * uz);

    constexpr int GS = (G + 31) / 32;
    float sg[GS];   // sqrt(center dist) - radius

    // ---- Phase 1: group distances; nearest group via one REDUX.MIN ----
    float bd2 = INF_F;
    unsigned bcode = 0;
#pragma unroll
    for (int s = 0; s < GS; s++) {
        int gi = s * 32 + lane;
        float4 cc = make_float4(0.0f, 0.0f, 0.0f, 0.0f);
        if (G >= 32 || gi < G) cc = __ldg(gc + gi);
        float dx = qx - cc.x, dy = qy - cc.y, dz = qz - cc.z;
        float d2 = fmaf(dx, dx, fmaf(dy, dy, dz * dz));
        float sgv = sqrtf(d2) - cc.w;
        if (!(G >= 32 || gi < G)) { d2 = INF_F; sgv = INF_F; }
        sg[s] = sgv;
        if (d2 < bd2) { bd2 = d2; bcode = (unsigned)(s << 5) | lane; }
    }
    unsigned kmin = (__float_as_uint(bd2) & 0xFFFFFF80u) | bcode;
    kmin = __reduce_min_sync(0xFFFFFFFFu, kmin);
    const int g0 = (int)(((kmin >> 5) & 3u) * 32u + (kmin & 31u));

    float d[K];
    int ixp[K];
#pragma unroll
    for (int i = 0; i < K; i++) { d[i] = INF_F; ixp[i] = 0; }

#define INSERT_POPS(MASK, TOTV, POSBASE)                                       \
    while (MASK) {                                                             \
        int sp_ = __ffs(MASK) - 1;                                             \
        MASK &= MASK - 1;                                                      \
        float cd_ = __shfl_sync(0xFFFFFFFFu, TOTV, sp_);                       \
        int ci_ = (POSBASE) + sp_;                                             \
        _Pragma("unroll") for (int i_ = 0; i_ < K; i_++)                       \
        {                                                                      \
            bool sw_ = cd_ < d[i_];                                            \
            float od_ = d[i_];                                                 \
            int oi_ = ixp[i_];                                                 \
            d[i_] = sw_ ? cd_ : od_;                                           \
            ixp[i_] = sw_ ? ci_ : oi_;                                         \
            cd_ = sw_ ? od_ : cd_;                                             \
            ci_ = sw_ ? oi_ : ci_;                                             \
        }                                                                      \
    }

    // ---- Warm-up: eval nearest group; ub = max of quad minima (>= 8th) ----
    {
        int pos = g0 * 32 + lane;
        float4 c = __ldg(sx + pos);
        float sd = fmaf(-qz, c.z, fmaf(-qy, c.y, fmaf(-qx, c.x, c.w)));
        float dxy = sqrtf(fmaxf(2.0f * (sd + qh), 0.0f));
        float4 nc = __ldg(sn + pos);
        float nd = fmaf(-uz, nc.z, fmaf(-uy, nc.y, fmaf(-ux, nc.x, nc.w)));
        float dn = sqrtf(fmaxf(2.0f * (nd + uh), 0.0f));
        float tot = dxy + 1.0f / (1.0f + __expf(-dn));

        float qm = fminf(tot, __shfl_xor_sync(0xFFFFFFFFu, tot, 1));
        qm = fminf(qm, __shfl_xor_sync(0xFFFFFFFFu, qm, 2));
        float ub = fmaxf(qm, __shfl_xor_sync(0xFFFFFFFFu, qm, 4));
        ub = fmaxf(ub, __shfl_xor_sync(0xFFFFFFFFu, ub, 8));
        ub = fmaxf(ub, __shfl_xor_sync(0xFFFFFFFFu, ub, 16));

        unsigned m2 = __ballot_sync(0xFFFFFFFFu, tot <= ub);
        INSERT_POPS(m2, tot, g0 * 32)
    }
    float kth = d[K - 1];
    float kth05 = kth - 0.5f;

    // ---- Phase 2: sphere-pruned sweep, one-ahead prefetch, lazy nrm ----
#pragma unroll
    for (int s = 0; s < GS; s++) {
        bool surv = (sg[s] < kth05) && (s * 32 + lane != g0);
        unsigned m = __ballot_sync(0xFFFFFFFFu, surv);
        if (!m) continue;
        int src = __ffs(m) - 1;
        m &= m - 1;
        float4 c = __ldg(sx + (s * 32 + src) * 32 + lane);
        while (true) {
            int nxt = m ? (__ffs(m) - 1) : -1;
            float4 cpre;
            if (nxt >= 0) cpre = __ldg(sx + (s * 32 + nxt) * 32 + lane);
            float sgl = __shfl_sync(0xFFFFFFFFu, sg[s], src);
            if (sgl < kth05) {                       // warp-uniform recheck
                int pos = (s * 32 + src) * 32 + lane;
                float sd = fmaf(-qz, c.z, fmaf(-qy, c.y, fmaf(-qx, c.x, c.w)));
                float dxy = sqrtf(fmaxf(2.0f * (sd + qh), 0.0f));
                float tot = INF_F;
                if (dxy < kth05) {
                    float4 nc = __ldg(sn + pos);
                    float nd = fmaf(-uz, nc.z,
                                    fmaf(-uy, nc.y, fmaf(-ux, nc.x, nc.w)));
                    float dn = sqrtf(fmaxf(2.0f * (nd + uh), 0.0f));
                    tot = dxy + 1.0f / (1.0f + __expf(-dn));
                }
                unsigned m2 = __ballot_sync(0xFFFFFFFFu, tot < kth);
                if (m2) {
                    INSERT_POPS(m2, tot, pos - lane)
                    kth = d[K - 1];
                    kth05 = kth - 0.5f;
                }
            }
            if (nxt < 0) break;
            src = nxt;
            m &= m - 1;
            c = cpre;
        }
    }
#undef INSERT_POPS

    if (lane == 0) {
        float r[K];
        float sum = 0.0f;
#pragma unroll
        for (int i = 0; i < K; i++) { r[i] = 1.0f / (d[i] + 1e-8f); sum += r[i]; }
        float inv = 1.0f / sum;
        const int* sid = g_sid + base + b * S;
        int o0 = sid[ixp[0]], o1 = sid[ixp[1]], o2 = sid[ixp[2]], o3 = sid[ixp[3]];
        int o4i = sid[ixp[4]], o5 = sid[ixp[5]], o6 = sid[ixp[6]], o7 = sid[ixp[7]];
        float4* o4 = (float4*)(g_wiv + wbase + ((size_t)b * N + n) * 16);
        o4[0] = make_float4(r[0] * inv, r[1] * inv, r[2] * inv, r[3] * inv);
        o4[1] = make_float4(r[4] * inv, r[5] * inv, r[6] * inv, r[7] * inv);
        o4[2] = make_float4(__int_as_float(o0), __int_as_float(o1),
                            __int_as_float(o2), __int_as_float(o3));
        o4[3] = make_float4(__int_as_float(o4i), __int_as_float(o5),
                            __int_as_float(o6), __int_as_float(o7));
    }
}

// ---------------------------------------------------------------------------
// Fused topk: all three stages; queries taken in morton-sorted order.
// blocks: [0,4096) stage2, [4096,5120) stage1, [5120,5376) stage0.
// ---------------------------------------------------------------------------
__global__ void __launch_bounds__(256, 6) topk_fused(
    const float* __restrict__ x0, const float* __restrict__ n0,
    const float* __restrict__ x1, const float* __restrict__ n1,
    const float* __restrict__ x2, const float* __restrict__ n2)
{
    const int bid = blockIdx.x;
    const int warp = threadIdx.x >> 5;
    const int lane = threadIdx.x & 31;
    if (bid < 4096) {
        int lb = bid, b = lb >> 11, qi = (lb & 2047) * 8 + warp;
        int n = (int)(unsigned)g_qsort[b * 16384 + qi];
        topk_query<4096, 128>(x0, n0, 16384, 0, 0, WOFF2, b, n, lane);
    } else if (bid < 5120) {
        int lb = bid - 4096, b = lb >> 9, qi = (lb & 511) * 8 + warp;
        int n = (int)(unsigned)g_qsort[32768 + b * 4096 + qi];
        topk_query<1024, 32>(x1, n1, 4096, 8192, 256, WOFF1, b, n, lane);
    } else {
        int lb = bid - 5120, b = lb >> 7, qi = (lb & 127) * 8 + warp;
        int n = (int)(unsigned)g_qsort[40960 + b * 1024 + qi];
        topk_query<256, 8>(x2, n2, 1024, 10240, 320, WOFF0, b, n, lane);
    }
}

// ---------------------------------------------------------------------------
// Interpolate: 64 lanes (float4 channels) per query, 4 queries per block.
// ---------------------------------------------------------------------------
__global__ void __launch_bounds__(256) interp_kernel(
    const float* __restrict__ p1, const float* __restrict__ p2,
    float* __restrict__ out, int N, int S, int wbase)
{
    const int b = blockIdx.y;
    const int g = threadIdx.x >> 6;
    const int l = threadIdx.x & 63;
    const int n = blockIdx.x * 4 + g;

    const float4* wv = (const float4*)(g_wiv + wbase + ((size_t)b * N + n) * 16);
    float4 w0 = __ldg(wv + 0), w1 = __ldg(wv + 1);
    float4 f0 = __ldg(wv + 2), f1 = __ldg(wv + 3);

    const float4* __restrict__ P = (const float4*)p2 + (size_t)b * S * (C / 4);
    float4 acc;
    {
        float4 r0 = __ldg(P + (size_t)__float_as_int(f0.x) * (C / 4) + l);
        acc.x = w0.x * r0.x; acc.y = w0.x * r0.y;
        acc.z = w0.x * r0.z; acc.w = w0.x * r0.w;
    }
#define GATHER(W, IDX)                                                         \
    {                                                                          \
        float4 r_ = __ldg(P + (size_t)__float_as_int(IDX) * (C / 4) + l);      \
        acc.x = fmaf(W, r_.x, acc.x); acc.y = fmaf(W, r_.y, acc.y);            \
        acc.z = fmaf(W, r_.z, acc.z); acc.w = fmaf(W, r_.w, acc.w);            \
    }
    GATHER(w0.y, f0.y) GATHER(w0.z, f0.z) GATHER(w0.w, f0.w)
    GATHER(w1.x, f1.x) GATHER(w1.y, f1.y) GATHER(w1.z, f1.z) GATHER(w1.w, f1.w)
#undef GATHER

    const size_t qo = ((size_t)b * N + n) * (C / 4) + l;
    float4 pv = __ldg((const float4*)p1 + qo);
    float4 o;
    o.x = (fmaxf(pv.x, acc.x) + (pv.x + acc.x) * 0.5f) * 0.5f;
    o.y = (fmaxf(pv.y, acc.y) + (pv.y + acc.y) * 0.5f) * 0.5f;
    o.z = (fmaxf(pv.z, acc.z) + (pv.z + acc.z) * 0.5f) * 0.5f;
    o.w = (fmaxf(pv.w, acc.w) + (pv.w + acc.w) * 0.5f) * 0.5f;
    ((float4*)out)[qo] = o;
}

// ---------------------------------------------------------------------------
extern "C" void kernel_launch(void* const* d_in, const int* in_sizes, int n_in,
                              void* d_out, int out_size)
{
    const int B = 2;
    const int Ns[4] = {16384, 4096, 1024, 256};
    const float* xyz[4] = {0, 0, 0, 0};
    const float* nrm[4] = {0, 0, 0, 0};
    const float* feat[4] = {0, 0, 0, 0};

    for (int i = 0; i < n_in; i++) {
        long long cnt = in_sizes[i];
        for (int r = 0; r < 4; r++) {
            long long small = (long long)B * Ns[r] * 3;
            long long big = (long long)B * Ns[r] * C;
            if (cnt == small) {
                if (!xyz[r]) xyz[r] = (const float*)d_in[i];
                else if (!nrm[r]) nrm[r] = (const float*)d_in[i];
                break;
            } else if (cnt == big) {
                if (!feat[r]) feat[r] = (const float*)d_in[i];
                break;
            }
        }
    }

    float* out = (float*)d_out;
    float *x1, *x2;
    cudaGetSymbolAddress((void**)&x1, g_x1);
    cudaGetSymbolAddress((void**)&x2, g_x2);

    // ---- Preprocess (2 launches) ----
    pack_kernel<<<(10752 + 43008 + 255) / 256, 256>>>(
        xyz[0], xyz[1], nrm[1], xyz[2], nrm[2], xyz[3], nrm[3]);
    csort_kernel<<<12, 1024>>>();

    // ---- All top-k stages in one launch ----
    topk_fused<<<5376, 256>>>(xyz[0], nrm[0], xyz[1], nrm[1], xyz[2], nrm[2]);

    // ---- Feature propagation chain ----
    interp_kernel<<<dim3(1024 / 4, B), 256>>>(feat[2], feat[3], x1, 1024, 256, WOFF0);
    interp_kernel<<<dim3(4096 / 4, B), 256>>>(feat[1], x1, x2, 4096, 1024, WOFF1);
    interp_kernel<<<dim3(16384 / 4, B), 256>>>(feat[0], x2, out, 16384, 4096, WOFF2);
}